// round 14
// baseline (speedup 1.0000x reference)
#include <cuda_runtime.h>
#include <cuda_fp16.h>
#include <math.h>

#define BB 64
#define LL 512
#define NSTEPS 20
#define NT 16
#define NPAIRS 136
#define NITEMS (NPAIRS * (BB / 2))   // 4352 (pair, batch-pair) items per step
#define PGRID  888                   // 148 SMs * 6 resident blocks

#define QSCALE 65535.0f
#define QINV   (1.0f / 65535.0f)

// Persistent device scratch (allocations are forbidden in kernel_launch).
// Pair-packed u16 state: for upper tile-pair p=(ti,tj), element (r,c) stores
// (A_hat[i,j], A_hat[j,i]) quantized to u16 in [0,1]. One uint4 = 4 elements.
__device__ uint4    g_S[(size_t)BB * NPAIRS * 256];     // 35.7 MB pair state (u16 pairs)
__device__ __half   g_Uh[(size_t)BB * NPAIRS * 1024];   // 17.8 MB fp16 Usym (pair layout)
__device__ __half2  g_RhoPp[NPAIRS * 1024];             // (rho[i,j], rho[j,i]) pair layout
__device__ unsigned g_Mbits[(size_t)BB * LL * NT];      // 2 MB mask bitmap
__device__ float    g_rp[2][(size_t)BB * LL * NT];      // double-buffered row partials
__device__ float    g_Lm[2][BB * LL];                   // double-buffered multipliers
__device__ float    g_at[NSTEPS];                       // alpha * lr_alpha^t
__device__ float    g_bt[NSTEPS];                       // belt  * lr_belt^t
__device__ uchar2   g_pairs[NPAIRS];                    // (ti, tj) per linear pair id

// ---------------------------------------------------------------------------
// L2 evict_last cache-policy helpers (pin reused state in L2).
__device__ __forceinline__ unsigned long long mk_pol() {
    unsigned long long p;
    asm("createpolicy.fractional.L2::evict_last.b64 %0, 1.0;" : "=l"(p));
    return p;
}
__device__ __forceinline__ uint4 ld_u4_el(const uint4* a, unsigned long long pol) {
    uint4 v;
    asm("ld.global.L2::cache_hint.v4.u32 {%0,%1,%2,%3}, [%4], %5;"
        : "=r"(v.x), "=r"(v.y), "=r"(v.z), "=r"(v.w)
        : "l"(a), "l"(pol));
    return v;
}
__device__ __forceinline__ void st_u4_el(uint4* a, uint4 v, unsigned long long pol) {
    asm volatile("st.global.L2::cache_hint.v4.u32 [%0], {%1,%2,%3,%4}, %5;"
                 :: "l"(a), "r"(v.x), "r"(v.y), "r"(v.z), "r"(v.w), "l"(pol)
                 : "memory");
}
__device__ __forceinline__ uint2 ld_u2_el(const __half* a, unsigned long long pol) {
    uint2 v;
    asm("ld.global.L2::cache_hint.v2.u32 {%0,%1}, [%2], %3;"
        : "=r"(v.x), "=r"(v.y) : "l"(a), "l"(pol));
    return v;
}

__device__ __forceinline__ unsigned qpack(float a, float b) {
    return __float2uint_rn(a * QSCALE) | (__float2uint_rn(b * QSCALE) << 16);
}
// Pack two q-domain values (already in [0,65535]) via PRMT.
__device__ __forceinline__ unsigned qpackq(float a, float b) {
    return __byte_perm(__float2uint_rn(a), __float2uint_rn(b), 0x5410);
}

// ---------------------------------------------------------------------------
// One-time: step coefficients + pair table.
__global__ void coef_k(const float* __restrict__ alpha_p,
                       const float* __restrict__ belt_p,
                       const float* __restrict__ lra_p,
                       const float* __restrict__ lrb_p) {
    const int t = threadIdx.x;
    if (t < NSTEPS) {
        g_at[t] = (*alpha_p) * powf(*lra_p, (float)t);
        g_bt[t] = (*belt_p)  * powf(*lrb_p, (float)t);
    }
    if (t < NPAIRS) {
        int p = t, a = 0;
        while (p >= NT - a) { p -= NT - a; a++; }
        g_pairs[t] = make_uchar2((unsigned char)a, (unsigned char)(a + p));
    }
}

// ---------------------------------------------------------------------------
// Packed rho in pair layout (static, once). One block per pair.
__global__ __launch_bounds__(256) void rhop_k(const float* __restrict__ rho) {
    const uchar2 pr = g_pairs[blockIdx.x];
    const int ti = pr.x, tj = pr.y;
    const int tid = threadIdx.x;
    const int r = tid >> 3, c0 = (tid & 7) * 4;
    const float4 nat = *(const float4*)(rho + (ti * 32 + r) * LL + tj * 32 + c0);
    const float natv[4] = {nat.x, nat.y, nat.z, nat.w};
#pragma unroll
    for (int k = 0; k < 4; k++) {
        const float tr = rho[(tj * 32 + c0 + k) * LL + ti * 32 + r];
        g_RhoPp[blockIdx.x * 1024 + r * 32 + c0 + k] = __floats2half2_rn(natv[k], tr);
    }
}

// ---------------------------------------------------------------------------
// Init: pair-packed u16 state S0 = (scores[i,j], scores[j,i]), Usym (fp16,
// pair layout), mask bitmap, and row-partials of A0 = sym(scores)*M.
__global__ __launch_bounds__(256) void init_k(const float* __restrict__ scores,
                                              const float* __restrict__ M,
                                              const float* __restrict__ s_p) {
    const int  p  = blockIdx.x;
    const uchar2 pr = g_pairs[p];
    const int ti = pr.x, tj = pr.y;
    const int  b    = blockIdx.y;
    const bool diag = (ti == tj);
    const int  tid  = threadIdx.x;
    const int  r    = tid >> 3, g = tid & 7, c0 = g * 4;
    const int  warp = tid >> 5, lane = tid & 31;

    __shared__ float sS[32][33];
    __shared__ float sRed[8][32];

    const size_t rowI  = (size_t)(b * LL) + ti * 32 + r;
    const size_t rowJ  = (size_t)(b * LL) + tj * 32 + r;
    const size_t baseI = rowI * LL + tj * 32 + c0;
    const size_t baseJ = rowJ * LL + ti * 32 + c0;

    const float4 scI = *(const float4*)(scores + baseI);
    const float4 scJ = diag ? scI : *(const float4*)(scores + baseJ);
    const float4 mI4 = *(const float4*)(M + baseI);

    sS[r][c0 + 0] = scJ.x; sS[r][c0 + 1] = scJ.y;
    sS[r][c0 + 2] = scJ.z; sS[r][c0 + 3] = scJ.w;

    // Pack mask bits (M is exactly 0.0/1.0).
    unsigned wI = (((mI4.x > 0.5f) ? 1u : 0u) | ((mI4.y > 0.5f) ? 2u : 0u) |
                   ((mI4.z > 0.5f) ? 4u : 0u) | ((mI4.w > 0.5f) ? 8u : 0u)) << c0;
    wI |= __shfl_xor_sync(0xffffffffu, wI, 1, 8);
    wI |= __shfl_xor_sync(0xffffffffu, wI, 2, 8);
    wI |= __shfl_xor_sync(0xffffffffu, wI, 4, 8);
    if (g == 0) g_Mbits[rowI * NT + tj] = wI;
    if (!diag) {
        const float4 mJ4 = *(const float4*)(M + baseJ);
        unsigned wJ = (((mJ4.x > 0.5f) ? 1u : 0u) | ((mJ4.y > 0.5f) ? 2u : 0u) |
                       ((mJ4.z > 0.5f) ? 4u : 0u) | ((mJ4.w > 0.5f) ? 8u : 0u)) << c0;
        wJ |= __shfl_xor_sync(0xffffffffu, wJ, 1, 8);
        wJ |= __shfl_xor_sync(0xffffffffu, wJ, 2, 8);
        wJ |= __shfl_xor_sync(0xffffffffu, wJ, 4, 8);
        if (g == 0) g_Mbits[rowJ * NT + ti] = wJ;
    }

    const float sv = *s_p;
    __syncthreads();

    const float scIv[4] = {scI.x, scI.y, scI.z, scI.w};
    const float mIv[4]  = {mI4.x, mI4.y, mI4.z, mI4.w};
    float a2v[4], uu[4], trv[4];
#pragma unroll
    for (int k = 0; k < 4; k++) {
        trv[k] = sS[c0 + k][r];                 // scores[j, i]
        const float avg = 0.5f * (scIv[k] + trv[k]);
        uu[k]  = avg - sv;
        a2v[k] = avg * mIv[k];                  // exact fp32 A0 values
    }
    const size_t pbase = (size_t)(b * NPAIRS + p);
    // Pair-packed quantized S0
    g_S[pbase * 256 + r * 8 + g] =
        make_uint4(qpack(scIv[0], trv[0]), qpack(scIv[1], trv[1]),
                   qpack(scIv[2], trv[2]), qpack(scIv[3], trv[3]));
    // Usym fp16, pair layout
    {
        __half2 h01 = __floats2half2_rn(uu[0], uu[1]);
        __half2 h23 = __floats2half2_rn(uu[2], uu[3]);
        uint2 pk; pk.x = *(unsigned*)&h01; pk.y = *(unsigned*)&h23;
        *(uint2*)(g_Uh + pbase * 1024 + r * 32 + c0) = pk;
    }

    // Row partials of A0 (buffer 1: step 0 reads (0+1)&1 = 1).
    {
        float v = (a2v[0] + a2v[1]) + (a2v[2] + a2v[3]);
        v += __shfl_down_sync(0xffffffffu, v, 4, 8);
        v += __shfl_down_sync(0xffffffffu, v, 2, 8);
        v += __shfl_down_sync(0xffffffffu, v, 1, 8);
        if (g == 0) g_rp[1][rowI * NT + tj] = v;
    }
    if (!diag) {
#pragma unroll
        for (int k = 0; k < 4; k++) {
            float v = a2v[k];
            v += __shfl_xor_sync(0xffffffffu, v, 16);
            v += __shfl_xor_sync(0xffffffffu, v, 8);
            if (lane < 8) sRed[warp][c0 + k] = v;
        }
        __syncthreads();
        if (tid < 32) {
            float s2 = 0.f;
#pragma unroll
            for (int w = 0; w < 8; w++) s2 += sRed[w][tid];
            g_rp[1][((size_t)(b * LL) + tj * 32 + tid) * NT + ti] = s2;
        }
    }
}

// ---------------------------------------------------------------------------
// One proximal step, persistent grid-stride over all (pair, batch-pair)
// items. Pair-packed u16 state, q-domain arithmetic. Per-block deterministic
// recompute of c (and Lm_t) for 128 rows by 128 threads.
template <bool FIRST>
__global__ __launch_bounds__(256, 6) void step2_k(const float* __restrict__ w_p,
                                                  int t) {
    const int tid  = threadIdx.x;
    const int r    = tid >> 3, g = tid & 7, c0 = g * 4;
    const int warp = tid >> 5, lane = tid & 31;

    __shared__ float sRed[2][8][32];
    __shared__ float sC[128];   // [batch*64 + (ti rows 0..31 | tj rows 32..63)]

    const unsigned long long pol = mk_pol();
    const float at  = g_at[t];
    const float atq = at * QSCALE;
    const float bc  = FIRST ? (*w_p) : g_bt[t - 1];
    const float* __restrict__ rpin  = g_rp[(t + 1) & 1];
    float*       __restrict__ rpout = g_rp[t & 1];
    const float* __restrict__ lmin  = g_Lm[(t + 1) & 1];
    float*       __restrict__ lmout = g_Lm[t & 1];
    constexpr float HQ = 0.5f * QINV;

    for (int it = blockIdx.x; it < NITEMS; it += PGRID) {
        const int p  = it % NPAIRS;
        const int b0 = (it / NPAIRS) * 2;
        const uchar2 pr = g_pairs[p];
        const int ti = pr.x, tj = pr.y;
        const bool diag = (ti == tj);

        const unsigned pb0   = (unsigned)(b0 * NPAIRS + p);
        const unsigned pb1   = pb0 + NPAIRS;
        const unsigned sidx0 = pb0 * 256u + (unsigned)(r * 8 + g);
        const unsigned sidx1 = pb1 * 256u + (unsigned)(r * 8 + g);

        // Hoist the long-latency loads (state + Usym) for MLP.
        const uint4 sq0 = ld_u4_el(g_S + sidx0, pol);
        const uint4 sq1 = ld_u4_el(g_S + sidx1, pol);
        const uint2 up0 = ld_u2_el(g_Uh + pb0 * 1024u + (unsigned)(r * 32 + c0), pol);
        const uint2 up1 = ld_u2_el(g_Uh + pb1 * 1024u + (unsigned)(r * 32 + c0), pol);

        // Shared thresholds (identical for both batches): rho * at, q-domain.
        float thx[4], thy[4];
        {
            const uint4 rp4 = *(const uint4*)(g_RhoPp + (unsigned)(p * 1024 + r * 32 + c0));
            const __half2* rh = (const __half2*)&rp4;
#pragma unroll
            for (int k = 0; k < 4; k++) {
                const float2 rk = __half22float2(rh[k]);
                thx[k] = rk.x * atq;
                thy[k] = rk.y * atq;
            }
        }

        // --- per-row c (and Lm_t): 4 warps, one row per thread ---
        if (tid < 128) {
            const int batch = tid >> 6;
            const int idx   = tid & 63;
            const int b     = b0 + batch;
            const int rowl  = (idx < 32) ? (ti * 32 + idx) : (tj * 32 + (idx - 32));
            const unsigned ro = (unsigned)(b * LL + rowl);
            const float* rpr = rpin + ro * (unsigned)NT;
            const float4 p0 = *(const float4*)(rpr + 0);
            const float4 p1 = *(const float4*)(rpr + 4);
            const float4 p2 = *(const float4*)(rpr + 8);
            const float4 p3 = *(const float4*)(rpr + 12);
            const float v = (((p0.x + p0.y) + (p0.z + p0.w)) +
                             ((p1.x + p1.y) + (p1.z + p1.w))) +
                            (((p2.x + p2.y) + (p2.z + p2.w)) +
                             ((p3.x + p3.y) + (p3.z + p3.w)));
            const float rd   = v - 1.0f;
            const float rpos = fmaxf(rd, 0.f);
            const float lm   = FIRST ? bc * rpos : lmin[ro] + bc * rpos;
            const float sg   = (rd > 0.f) ? 1.f : ((rd < 0.f) ? -1.f : 0.f);
            sC[tid] = lm * sg;
            if (diag && idx < 32) lmout[ro] = lm;
        }
        __syncthreads();

#pragma unroll
        for (int bb = 0; bb < 2; bb++) {
            const uint4    sq = bb ? sq1 : sq0;
            const uint2    up = bb ? up1 : up0;
            const unsigned mw =
                g_Mbits[(unsigned)((b0 + bb) * LL + ti * 32 + r) * (unsigned)NT + tj];
            const float*   cb = sC + bb * 64;
            const float    ci = cb[r];
            const float4  cj4 = *(const float4*)(cb + 32 + c0);
            const float   cjv[4] = {cj4.x, cj4.y, cj4.z, cj4.w};
            const unsigned sqs[4] = {sq.x, sq.y, sq.z, sq.w};
            const float2 u01 = __half22float2(*(const __half2*)&up.x);
            const float2 u23 = __half22float2(*(const __half2*)&up.y);
            const float uv[4] = {u01.x, u01.y, u23.x, u23.y};

            uint4 outq;
            unsigned* oq = (unsigned*)&outq;
            float v = 0.f;       // row-partial accumulator (q units)
            float a2q[4];
#pragma unroll
            for (int k = 0; k < 4; k++) {
                const bool  mk   = (mw >> (c0 + k)) & 1u;
                const float du   = uv[k] - (ci + cjv[k]);
                const float mult = mk ? fmaf(at, du, 1.f) : 1.f;
                const float spq  = (float)(sqs[k] & 0xffffu);
                const float stq  = (float)(sqs[k] >> 16);
                const float pv = fminf(fmaxf(fabsf(spq * mult) - thx[k], 0.f), QSCALE);
                const float tv = fminf(fmaxf(fabsf(stq * mult) - thy[k], 0.f), QSCALE);
                oq[k]  = qpackq(pv, tv);
                a2q[k] = mk ? (pv + tv) : 0.f;
                v += a2q[k];
            }

            st_u4_el(g_S + (bb ? sidx1 : sidx0), outq, pol);

            // Row partials of A2, ti rows.
            v += __shfl_down_sync(0xffffffffu, v, 4, 8);
            v += __shfl_down_sync(0xffffffffu, v, 2, 8);
            v += __shfl_down_sync(0xffffffffu, v, 1, 8);
            if (g == 0)
                rpout[(unsigned)((b0 + bb) * LL + ti * 32 + r) * (unsigned)NT + tj] = v * HQ;
            // tj rows (off-diag only; diagonal would double count).
            if (!diag) {
#pragma unroll
                for (int k = 0; k < 4; k++) {
                    float w2 = a2q[k];
                    w2 += __shfl_xor_sync(0xffffffffu, w2, 16);
                    w2 += __shfl_xor_sync(0xffffffffu, w2, 8);
                    if (lane < 8) sRed[bb][warp][c0 + k] = w2;
                }
            }
        }

        __syncthreads();   // sRed writes visible; sC reads of this item done
        if (!diag && tid < 64) {
            const int bb = tid >> 5, col = tid & 31;
            float s2 = 0.f;
#pragma unroll
            for (int w = 0; w < 8; w++) s2 += sRed[bb][w][col];
            rpout[(unsigned)((b0 + bb) * LL + tj * 32 + col) * (unsigned)NT + ti] = s2 * HQ;
        }
        __syncthreads();   // sRed reads done before next item's writes
    }
}

// ---------------------------------------------------------------------------
// Last proximal step: computes A2 and writes dense output only.
__global__ __launch_bounds__(256, 7) void stepL_k(int t, float* __restrict__ out) {
    const int  p  = blockIdx.x;
    const uchar2 pr = g_pairs[p];
    const int ti = pr.x, tj = pr.y;
    const int  b    = blockIdx.y;
    const bool diag = (ti == tj);
    const int  tid  = threadIdx.x;
    const int  r    = tid >> 3, g = tid & 7, c0 = g * 4;

    __shared__ float sStage[32][33];
    __shared__ float sC[64];

    const size_t rowI = (size_t)(b * LL) + ti * 32 + r;
    const unsigned long long pol = mk_pol();

    const size_t pbase = (size_t)(b * NPAIRS + p);
    const size_t sidx  = pbase * 256 + r * 8 + g;
    const uint4  sq  = ld_u4_el(g_S + sidx, pol);
    const uint2  up  = ld_u2_el(g_Uh + pbase * 1024 + r * 32 + c0, pol);
    const uint4  rp4 = *(const uint4*)(g_RhoPp + p * 1024 + r * 32 + c0);
    const unsigned mw = g_Mbits[rowI * NT + tj];

    const float at  = g_at[t];
    const float atq = at * QSCALE;

    if (tid < 64) {
        const int rowl = (tid < 32) ? (ti * 32 + tid) : (tj * 32 + (tid - 32));
        const float* rpr = g_rp[(t + 1) & 1] + ((size_t)(b * LL) + rowl) * NT;
        const float4 p0 = *(const float4*)(rpr + 0);
        const float4 p1 = *(const float4*)(rpr + 4);
        const float4 p2 = *(const float4*)(rpr + 8);
        const float4 p3 = *(const float4*)(rpr + 12);
        const float v = (((p0.x + p0.y) + (p0.z + p0.w)) +
                         ((p1.x + p1.y) + (p1.z + p1.w))) +
                        (((p2.x + p2.y) + (p2.z + p2.w)) +
                         ((p3.x + p3.y) + (p3.z + p3.w)));
        const float rd   = v - 1.0f;
        const float rpos = fmaxf(rd, 0.f);
        const float lm = g_Lm[(t + 1) & 1][b * LL + rowl] + g_bt[t - 1] * rpos;
        const float sg = (rd > 0.f) ? 1.f : ((rd < 0.f) ? -1.f : 0.f);
        sC[tid] = lm * sg;
    }
    __syncthreads();

    const float ci = sC[r];
    const float4 cj4 = *(const float4*)(sC + 32 + c0);
    const float cjv[4] = {cj4.x, cj4.y, cj4.z, cj4.w};
    const unsigned sqs[4] = {sq.x, sq.y, sq.z, sq.w};
    const __half2* rh = (const __half2*)&rp4;
    const float2 u01 = __half22float2(*(const __half2*)&up.x);
    const float2 u23 = __half22float2(*(const __half2*)&up.y);
    const float uv[4] = {u01.x, u01.y, u23.x, u23.y};

    constexpr float HQ = 0.5f * QINV;
    float a2[4];
#pragma unroll
    for (int k = 0; k < 4; k++) {
        const bool  mk   = (mw >> (c0 + k)) & 1u;
        const float du   = uv[k] - (ci + cjv[k]);
        const float mult = mk ? fmaf(at, du, 1.f) : 1.f;
        const float2 rk  = __half22float2(rh[k]);
        const float spq  = (float)(sqs[k] & 0xffffu);
        const float stq  = (float)(sqs[k] >> 16);
        const float pv = fminf(fmaxf(fabsf(spq * mult) - rk.x * atq, 0.f), QSCALE);
        const float tv = fminf(fmaxf(fabsf(stq * mult) - rk.y * atq, 0.f), QSCALE);
        a2[k] = mk ? (pv + tv) * HQ : 0.f;
        sStage[c0 + k][r] = a2[k];
    }

    const size_t baseI = rowI * LL + tj * 32 + c0;
    *(float4*)(out + baseI) = make_float4(a2[0], a2[1], a2[2], a2[3]);
    __syncthreads();
    if (!diag) {
        const size_t baseJ = ((size_t)(b * LL) + tj * 32 + r) * LL + ti * 32 + c0;
        *(float4*)(out + baseJ) = make_float4(sStage[r][c0 + 0], sStage[r][c0 + 1],
                                              sStage[r][c0 + 2], sStage[r][c0 + 3]);
    }
}

// ---------------------------------------------------------------------------
extern "C" void kernel_launch(void* const* d_in, const int* in_sizes, int n_in,
                              void* d_out, int out_size) {
    const float* scores  = (const float*)d_in[0];
    const float* M       = (const float*)d_in[1];
    const float* s_p     = (const float*)d_in[2];
    const float* w_p     = (const float*)d_in[3];
    const float* rho     = (const float*)d_in[4];
    const float* alpha_p = (const float*)d_in[5];
    const float* belt_p  = (const float*)d_in[6];
    const float* lra_p   = (const float*)d_in[7];
    const float* lrb_p   = (const float*)d_in[8];
    float* out = (float*)d_out;
    (void)in_sizes; (void)n_in; (void)out_size;

    coef_k<<<1, 256>>>(alpha_p, belt_p, lra_p, lrb_p);
    rhop_k<<<NPAIRS, 256>>>(rho);

    init_k<<<dim3(NPAIRS, BB), 256>>>(scores, M, s_p);

    step2_k<true><<<PGRID, 256>>>(w_p, 0);
    for (int t = 1; t < NSTEPS - 1; t++)
        step2_k<false><<<PGRID, 256>>>(w_p, t);
    stepL_k<<<dim3(NPAIRS, BB), 256>>>(NSTEPS - 1, out);
}

// round 15
// speedup vs baseline: 1.1033x; 1.1033x over previous
#include <cuda_runtime.h>
#include <cuda_fp16.h>
#include <math.h>

#define BB 64
#define LL 512
#define NSTEPS 20
#define NT 16
#define NPAIRS 136

#define QSCALE 65535.0f
#define QINV   (1.0f / 65535.0f)

// Persistent device scratch (allocations are forbidden in kernel_launch).
// Pair-packed u16 state: for upper tile-pair p=(ti,tj), element (r,c) stores
// (A_hat[i,j], A_hat[j,i]) quantized to u16 in [0,1]. One uint4 = 4 elements.
__device__ uint4    g_S[(size_t)BB * NPAIRS * 256];     // 35.7 MB pair state (u16 pairs)
__device__ __half   g_Uh[(size_t)BB * NPAIRS * 1024];   // 17.8 MB fp16 Usym (pair layout)
__device__ __half2  g_RhoPp[NPAIRS * 1024];             // (rho[i,j], rho[j,i]) pair layout
__device__ unsigned g_Mbits[(size_t)BB * LL * NT];      // 2 MB mask bitmap
__device__ float    g_rp[2][(size_t)BB * LL * NT];      // double-buffered row partials
__device__ float    g_Lm[2][BB * LL];                   // double-buffered multipliers
__device__ float    g_at[NSTEPS];                       // alpha * lr_alpha^t
__device__ float    g_bt[NSTEPS];                       // belt  * lr_belt^t
__device__ uchar2   g_pairs[NPAIRS];                    // (ti, tj) per linear pair id

// ---------------------------------------------------------------------------
// L2 evict_last cache-policy helpers (pin reused state in L2).
__device__ __forceinline__ unsigned long long mk_pol() {
    unsigned long long p;
    asm("createpolicy.fractional.L2::evict_last.b64 %0, 1.0;" : "=l"(p));
    return p;
}
__device__ __forceinline__ uint4 ld_u4_el(const uint4* a, unsigned long long pol) {
    uint4 v;
    asm("ld.global.L2::cache_hint.v4.u32 {%0,%1,%2,%3}, [%4], %5;"
        : "=r"(v.x), "=r"(v.y), "=r"(v.z), "=r"(v.w)
        : "l"(a), "l"(pol));
    return v;
}
__device__ __forceinline__ void st_u4_el(uint4* a, uint4 v, unsigned long long pol) {
    asm volatile("st.global.L2::cache_hint.v4.u32 [%0], {%1,%2,%3,%4}, %5;"
                 :: "l"(a), "r"(v.x), "r"(v.y), "r"(v.z), "r"(v.w), "l"(pol)
                 : "memory");
}
__device__ __forceinline__ uint2 ld_u2_el(const __half* a, unsigned long long pol) {
    uint2 v;
    asm("ld.global.L2::cache_hint.v2.u32 {%0,%1}, [%2], %3;"
        : "=r"(v.x), "=r"(v.y) : "l"(a), "l"(pol));
    return v;
}

__device__ __forceinline__ unsigned qpack(float a, float b) {
    return __float2uint_rn(a * QSCALE) | (__float2uint_rn(b * QSCALE) << 16);
}
// Pack two q-domain values (already in [0,65535]) via PRMT.
__device__ __forceinline__ unsigned qpackq(float a, float b) {
    return __byte_perm(__float2uint_rn(a), __float2uint_rn(b), 0x5410);
}

// ---------------------------------------------------------------------------
// One-time: step coefficients + pair table.
__global__ void coef_k(const float* __restrict__ alpha_p,
                       const float* __restrict__ belt_p,
                       const float* __restrict__ lra_p,
                       const float* __restrict__ lrb_p) {
    const int t = threadIdx.x;
    if (t < NSTEPS) {
        g_at[t] = (*alpha_p) * powf(*lra_p, (float)t);
        g_bt[t] = (*belt_p)  * powf(*lrb_p, (float)t);
    }
    if (t < NPAIRS) {
        int p = t, a = 0;
        while (p >= NT - a) { p -= NT - a; a++; }
        g_pairs[t] = make_uchar2((unsigned char)a, (unsigned char)(a + p));
    }
}

// ---------------------------------------------------------------------------
// Packed rho in pair layout (static, once). One block per pair.
__global__ __launch_bounds__(256) void rhop_k(const float* __restrict__ rho) {
    const uchar2 pr = g_pairs[blockIdx.x];
    const int ti = pr.x, tj = pr.y;
    const int tid = threadIdx.x;
    const int r = tid >> 3, c0 = (tid & 7) * 4;
    const float4 nat = *(const float4*)(rho + (ti * 32 + r) * LL + tj * 32 + c0);
    const float natv[4] = {nat.x, nat.y, nat.z, nat.w};
#pragma unroll
    for (int k = 0; k < 4; k++) {
        const float tr = rho[(tj * 32 + c0 + k) * LL + ti * 32 + r];
        g_RhoPp[blockIdx.x * 1024 + r * 32 + c0 + k] = __floats2half2_rn(natv[k], tr);
    }
}

// ---------------------------------------------------------------------------
// Init: pair-packed u16 state S0 = (scores[i,j], scores[j,i]), Usym (fp16,
// pair layout), mask bitmap, and row-partials of A0 = sym(scores)*M.
__global__ __launch_bounds__(256) void init_k(const float* __restrict__ scores,
                                              const float* __restrict__ M,
                                              const float* __restrict__ s_p) {
    const int  p  = blockIdx.x;
    const uchar2 pr = g_pairs[p];
    const int ti = pr.x, tj = pr.y;
    const int  b    = blockIdx.y;
    const bool diag = (ti == tj);
    const int  tid  = threadIdx.x;
    const int  r    = tid >> 3, g = tid & 7, c0 = g * 4;
    const int  warp = tid >> 5, lane = tid & 31;

    __shared__ float sS[32][33];
    __shared__ float sRed[8][32];

    const size_t rowI  = (size_t)(b * LL) + ti * 32 + r;
    const size_t rowJ  = (size_t)(b * LL) + tj * 32 + r;
    const size_t baseI = rowI * LL + tj * 32 + c0;
    const size_t baseJ = rowJ * LL + ti * 32 + c0;

    const float4 scI = *(const float4*)(scores + baseI);
    const float4 scJ = diag ? scI : *(const float4*)(scores + baseJ);
    const float4 mI4 = *(const float4*)(M + baseI);

    sS[r][c0 + 0] = scJ.x; sS[r][c0 + 1] = scJ.y;
    sS[r][c0 + 2] = scJ.z; sS[r][c0 + 3] = scJ.w;

    // Pack mask bits (M is exactly 0.0/1.0).
    unsigned wI = (((mI4.x > 0.5f) ? 1u : 0u) | ((mI4.y > 0.5f) ? 2u : 0u) |
                   ((mI4.z > 0.5f) ? 4u : 0u) | ((mI4.w > 0.5f) ? 8u : 0u)) << c0;
    wI |= __shfl_xor_sync(0xffffffffu, wI, 1, 8);
    wI |= __shfl_xor_sync(0xffffffffu, wI, 2, 8);
    wI |= __shfl_xor_sync(0xffffffffu, wI, 4, 8);
    if (g == 0) g_Mbits[rowI * NT + tj] = wI;
    if (!diag) {
        const float4 mJ4 = *(const float4*)(M + baseJ);
        unsigned wJ = (((mJ4.x > 0.5f) ? 1u : 0u) | ((mJ4.y > 0.5f) ? 2u : 0u) |
                       ((mJ4.z > 0.5f) ? 4u : 0u) | ((mJ4.w > 0.5f) ? 8u : 0u)) << c0;
        wJ |= __shfl_xor_sync(0xffffffffu, wJ, 1, 8);
        wJ |= __shfl_xor_sync(0xffffffffu, wJ, 2, 8);
        wJ |= __shfl_xor_sync(0xffffffffu, wJ, 4, 8);
        if (g == 0) g_Mbits[rowJ * NT + ti] = wJ;
    }

    const float sv = *s_p;
    __syncthreads();

    const float scIv[4] = {scI.x, scI.y, scI.z, scI.w};
    const float mIv[4]  = {mI4.x, mI4.y, mI4.z, mI4.w};
    float a2v[4], uu[4], trv[4];
#pragma unroll
    for (int k = 0; k < 4; k++) {
        trv[k] = sS[c0 + k][r];                 // scores[j, i]
        const float avg = 0.5f * (scIv[k] + trv[k]);
        uu[k]  = avg - sv;
        a2v[k] = avg * mIv[k];                  // exact fp32 A0 values
    }
    const size_t pbase = (size_t)(b * NPAIRS + p);
    // Pair-packed quantized S0
    g_S[pbase * 256 + r * 8 + g] =
        make_uint4(qpack(scIv[0], trv[0]), qpack(scIv[1], trv[1]),
                   qpack(scIv[2], trv[2]), qpack(scIv[3], trv[3]));
    // Usym fp16, pair layout
    {
        __half2 h01 = __floats2half2_rn(uu[0], uu[1]);
        __half2 h23 = __floats2half2_rn(uu[2], uu[3]);
        uint2 pk; pk.x = *(unsigned*)&h01; pk.y = *(unsigned*)&h23;
        *(uint2*)(g_Uh + pbase * 1024 + r * 32 + c0) = pk;
    }

    // Row partials of A0 (buffer 1: step 0 reads (0+1)&1 = 1).
    {
        float v = (a2v[0] + a2v[1]) + (a2v[2] + a2v[3]);
        v += __shfl_down_sync(0xffffffffu, v, 4, 8);
        v += __shfl_down_sync(0xffffffffu, v, 2, 8);
        v += __shfl_down_sync(0xffffffffu, v, 1, 8);
        if (g == 0) g_rp[1][rowI * NT + tj] = v;
    }
    if (!diag) {
#pragma unroll
        for (int k = 0; k < 4; k++) {
            float v = a2v[k];
            v += __shfl_xor_sync(0xffffffffu, v, 16);
            v += __shfl_xor_sync(0xffffffffu, v, 8);
            if (lane < 8) sRed[warp][c0 + k] = v;
        }
        __syncthreads();
        if (tid < 32) {
            float s2 = 0.f;
#pragma unroll
            for (int w = 0; w < 8; w++) s2 += sRed[w][tid];
            g_rp[1][((size_t)(b * LL) + tj * 32 + tid) * NT + ti] = s2;
        }
    }
}

// ---------------------------------------------------------------------------
// One proximal step, 4 batches per block (one pair x batches b0..b0+3).
// Pair-packed u16 state, q-domain arithmetic. Per-block deterministic
// recompute of c (and Lm_t) for 256 rows by all 256 threads (perfect fit).
template <bool FIRST>
__global__ __launch_bounds__(256, 4) void step4_k(const float* __restrict__ w_p,
                                                  int t) {
    const int  p  = blockIdx.x;
    const uchar2 pr = g_pairs[p];
    const int ti = pr.x, tj = pr.y;
    const int  b0   = blockIdx.y * 4;
    const bool diag = (ti == tj);
    const int  tid  = threadIdx.x;
    const int  r    = tid >> 3, g = tid & 7, c0 = g * 4;
    const int  warp = tid >> 5, lane = tid & 31;

    __shared__ float sRed[4][8][32];
    __shared__ float sC[256];   // [batch*64 + (ti rows 0..31 | tj rows 32..63)]

    const unsigned long long pol = mk_pol();

    const unsigned pb0 = (unsigned)(b0 * NPAIRS + p);
    const unsigned eoff = (unsigned)(r * 8 + g);
    const unsigned uoff = (unsigned)(r * 32 + c0);

    // Hoist the long-latency loads (state + Usym) for MLP (12 LDGs in flight).
    uint4 sq[4];
    uint2 up[4];
#pragma unroll
    for (int bb = 0; bb < 4; bb++) {
        const unsigned pb = pb0 + (unsigned)(bb * NPAIRS);
        sq[bb] = ld_u4_el(g_S + pb * 256u + eoff, pol);
        up[bb] = ld_u2_el(g_Uh + pb * 1024u + uoff, pol);
    }

    const float at  = g_at[t];
    const float atq = at * QSCALE;

    // Shared thresholds (identical for all batches): rho * at, q-domain.
    float thx[4], thy[4];
    {
        const uint4 rp4 = *(const uint4*)(g_RhoPp + (unsigned)(p * 1024) + uoff);
        const __half2* rh = (const __half2*)&rp4;
#pragma unroll
        for (int k = 0; k < 4; k++) {
            const float2 rk = __half22float2(rh[k]);
            thx[k] = rk.x * atq;
            thy[k] = rk.y * atq;
        }
    }

    // --- per-row c (and Lm_t): all 256 threads, one row each, deterministic ---
    {
        const int batch = tid >> 6;
        const int idx   = tid & 63;
        const int b     = b0 + batch;
        const int rowl  = (idx < 32) ? (ti * 32 + idx) : (tj * 32 + (idx - 32));
        const unsigned ro = (unsigned)(b * LL + rowl);
        const float* rpr = g_rp[(t + 1) & 1] + ro * (unsigned)NT;
        const float4 p0 = *(const float4*)(rpr + 0);
        const float4 p1 = *(const float4*)(rpr + 4);
        const float4 p2 = *(const float4*)(rpr + 8);
        const float4 p3 = *(const float4*)(rpr + 12);
        const float v = (((p0.x + p0.y) + (p0.z + p0.w)) +
                         ((p1.x + p1.y) + (p1.z + p1.w))) +
                        (((p2.x + p2.y) + (p2.z + p2.w)) +
                         ((p3.x + p3.y) + (p3.z + p3.w)));
        const float rd   = v - 1.0f;
        const float rpos = fmaxf(rd, 0.f);
        float lm;
        if (FIRST) lm = (*w_p) * rpos;
        else       lm = g_Lm[(t + 1) & 1][ro] + g_bt[t - 1] * rpos;
        const float sg = (rd > 0.f) ? 1.f : ((rd < 0.f) ? -1.f : 0.f);
        sC[tid] = lm * sg;
        if (diag && idx < 32) g_Lm[t & 1][ro] = lm;
    }
    __syncthreads();

    constexpr float HQ = 0.5f * QINV;
    float* __restrict__ rpout = g_rp[t & 1];

#pragma unroll
    for (int bb = 0; bb < 4; bb++) {
        const unsigned mw =
            g_Mbits[(unsigned)((b0 + bb) * LL + ti * 32 + r) * (unsigned)NT + tj];
        const float*   cb = sC + bb * 64;
        const float    ci = cb[r];
        const float4  cj4 = *(const float4*)(cb + 32 + c0);
        const float   cjv[4] = {cj4.x, cj4.y, cj4.z, cj4.w};
        const unsigned sqs[4] = {sq[bb].x, sq[bb].y, sq[bb].z, sq[bb].w};
        const float2 u01 = __half22float2(*(const __half2*)&up[bb].x);
        const float2 u23 = __half22float2(*(const __half2*)&up[bb].y);
        const float uv[4] = {u01.x, u01.y, u23.x, u23.y};

        uint4 outq;
        unsigned* oq = (unsigned*)&outq;
        float v = 0.f;       // row-partial accumulator (q units)
        float a2q[4];
#pragma unroll
        for (int k = 0; k < 4; k++) {
            const bool  mk   = (mw >> (c0 + k)) & 1u;
            const float du   = uv[k] - (ci + cjv[k]);
            const float mult = mk ? fmaf(at, du, 1.f) : 1.f;
            const float spq  = (float)(sqs[k] & 0xffffu);
            const float stq  = (float)(sqs[k] >> 16);
            const float pv = fminf(fmaxf(fabsf(spq * mult) - thx[k], 0.f), QSCALE);
            const float tv = fminf(fmaxf(fabsf(stq * mult) - thy[k], 0.f), QSCALE);
            oq[k]  = qpackq(pv, tv);
            a2q[k] = mk ? (pv + tv) : 0.f;
            v += a2q[k];
        }

        st_u4_el(g_S + (pb0 + (unsigned)(bb * NPAIRS)) * 256u + eoff, outq, pol);

        // Row partials of A2, ti rows.
        v += __shfl_down_sync(0xffffffffu, v, 4, 8);
        v += __shfl_down_sync(0xffffffffu, v, 2, 8);
        v += __shfl_down_sync(0xffffffffu, v, 1, 8);
        if (g == 0)
            rpout[(unsigned)((b0 + bb) * LL + ti * 32 + r) * (unsigned)NT + tj] = v * HQ;
        // tj rows (off-diag only; diagonal would double count).
        if (!diag) {
#pragma unroll
            for (int k = 0; k < 4; k++) {
                float w2 = a2q[k];
                w2 += __shfl_xor_sync(0xffffffffu, w2, 16);
                w2 += __shfl_xor_sync(0xffffffffu, w2, 8);
                if (lane < 8) sRed[bb][warp][c0 + k] = w2;
            }
        }
    }

    if (!diag) {
        __syncthreads();
        if (tid < 128) {
            const int bb = tid >> 5, col = tid & 31;
            float s2 = 0.f;
#pragma unroll
            for (int w = 0; w < 8; w++) s2 += sRed[bb][w][col];
            rpout[(unsigned)((b0 + bb) * LL + tj * 32 + col) * (unsigned)NT + ti] = s2 * HQ;
        }
    }
}

// ---------------------------------------------------------------------------
// Last proximal step: computes A2 and writes dense output only.
__global__ __launch_bounds__(256, 7) void stepL_k(int t, float* __restrict__ out) {
    const int  p  = blockIdx.x;
    const uchar2 pr = g_pairs[p];
    const int ti = pr.x, tj = pr.y;
    const int  b    = blockIdx.y;
    const bool diag = (ti == tj);
    const int  tid  = threadIdx.x;
    const int  r    = tid >> 3, g = tid & 7, c0 = g * 4;

    __shared__ float sStage[32][33];
    __shared__ float sC[64];

    const size_t rowI = (size_t)(b * LL) + ti * 32 + r;
    const unsigned long long pol = mk_pol();

    const size_t pbase = (size_t)(b * NPAIRS + p);
    const size_t sidx  = pbase * 256 + r * 8 + g;
    const uint4  sq  = ld_u4_el(g_S + sidx, pol);
    const uint2  up  = ld_u2_el(g_Uh + pbase * 1024 + r * 32 + c0, pol);
    const uint4  rp4 = *(const uint4*)(g_RhoPp + p * 1024 + r * 32 + c0);
    const unsigned mw = g_Mbits[rowI * NT + tj];

    const float at  = g_at[t];
    const float atq = at * QSCALE;

    if (tid < 64) {
        const int rowl = (tid < 32) ? (ti * 32 + tid) : (tj * 32 + (tid - 32));
        const float* rpr = g_rp[(t + 1) & 1] + ((size_t)(b * LL) + rowl) * NT;
        const float4 p0 = *(const float4*)(rpr + 0);
        const float4 p1 = *(const float4*)(rpr + 4);
        const float4 p2 = *(const float4*)(rpr + 8);
        const float4 p3 = *(const float4*)(rpr + 12);
        const float v = (((p0.x + p0.y) + (p0.z + p0.w)) +
                         ((p1.x + p1.y) + (p1.z + p1.w))) +
                        (((p2.x + p2.y) + (p2.z + p2.w)) +
                         ((p3.x + p3.y) + (p3.z + p3.w)));
        const float rd   = v - 1.0f;
        const float rpos = fmaxf(rd, 0.f);
        const float lm = g_Lm[(t + 1) & 1][b * LL + rowl] + g_bt[t - 1] * rpos;
        const float sg = (rd > 0.f) ? 1.f : ((rd < 0.f) ? -1.f : 0.f);
        sC[tid] = lm * sg;
    }
    __syncthreads();

    const float ci = sC[r];
    const float4 cj4 = *(const float4*)(sC + 32 + c0);
    const float cjv[4] = {cj4.x, cj4.y, cj4.z, cj4.w};
    const unsigned sqs[4] = {sq.x, sq.y, sq.z, sq.w};
    const __half2* rh = (const __half2*)&rp4;
    const float2 u01 = __half22float2(*(const __half2*)&up.x);
    const float2 u23 = __half22float2(*(const __half2*)&up.y);
    const float uv[4] = {u01.x, u01.y, u23.x, u23.y};

    constexpr float HQ = 0.5f * QINV;
    float a2[4];
#pragma unroll
    for (int k = 0; k < 4; k++) {
        const bool  mk   = (mw >> (c0 + k)) & 1u;
        const float du   = uv[k] - (ci + cjv[k]);
        const float mult = mk ? fmaf(at, du, 1.f) : 1.f;
        const float2 rk  = __half22float2(rh[k]);
        const float spq  = (float)(sqs[k] & 0xffffu);
        const float stq  = (float)(sqs[k] >> 16);
        const float pv = fminf(fmaxf(fabsf(spq * mult) - rk.x * atq, 0.f), QSCALE);
        const float tv = fminf(fmaxf(fabsf(stq * mult) - rk.y * atq, 0.f), QSCALE);
        a2[k] = mk ? (pv + tv) * HQ : 0.f;
        sStage[c0 + k][r] = a2[k];
    }

    const size_t baseI = rowI * LL + tj * 32 + c0;
    *(float4*)(out + baseI) = make_float4(a2[0], a2[1], a2[2], a2[3]);
    __syncthreads();
    if (!diag) {
        const size_t baseJ = ((size_t)(b * LL) + tj * 32 + r) * LL + ti * 32 + c0;
        *(float4*)(out + baseJ) = make_float4(sStage[r][c0 + 0], sStage[r][c0 + 1],
                                              sStage[r][c0 + 2], sStage[r][c0 + 3]);
    }
}

// ---------------------------------------------------------------------------
extern "C" void kernel_launch(void* const* d_in, const int* in_sizes, int n_in,
                              void* d_out, int out_size) {
    const float* scores  = (const float*)d_in[0];
    const float* M       = (const float*)d_in[1];
    const float* s_p     = (const float*)d_in[2];
    const float* w_p     = (const float*)d_in[3];
    const float* rho     = (const float*)d_in[4];
    const float* alpha_p = (const float*)d_in[5];
    const float* belt_p  = (const float*)d_in[6];
    const float* lra_p   = (const float*)d_in[7];
    const float* lrb_p   = (const float*)d_in[8];
    float* out = (float*)d_out;
    (void)in_sizes; (void)n_in; (void)out_size;

    coef_k<<<1, 256>>>(alpha_p, belt_p, lra_p, lrb_p);
    rhop_k<<<NPAIRS, 256>>>(rho);

    init_k<<<dim3(NPAIRS, BB), 256>>>(scores, M, s_p);

    dim3 grid4(NPAIRS, BB / 4);
    step4_k<true><<<grid4, 256>>>(w_p, 0);
    for (int t = 1; t < NSTEPS - 1; t++)
        step4_k<false><<<grid4, 256>>>(w_p, t);
    stepL_k<<<dim3(NPAIRS, BB), 256>>>(NSTEPS - 1, out);
}

// round 16
// speedup vs baseline: 1.1233x; 1.0182x over previous
#include <cuda_runtime.h>
#include <cuda_fp16.h>
#include <math.h>

#define BB 64
#define LL 512
#define NSTEPS 20
#define NT 16
#define NPAIRS 136

#define QSCALE 65535.0f
#define QINV   (1.0f / 65535.0f)

// Persistent device scratch (allocations are forbidden in kernel_launch).
// Pair-packed u16 state: for upper tile-pair p=(ti,tj), element (r,c) stores
// (A_hat[i,j], A_hat[j,i]) quantized to u16 in [0,1]. One uint4 = 4 elements.
__device__ uint4    g_S[(size_t)BB * NPAIRS * 256];     // 35.7 MB pair state (u16 pairs)
__device__ __half   g_Uh[(size_t)BB * NPAIRS * 1024];   // 17.8 MB fp16 Usym (pair layout)
__device__ __half2  g_RhoPp[NPAIRS * 1024];             // (rho[i,j], rho[j,i]) pair layout
__device__ unsigned g_Mbits[(size_t)BB * LL * NT];      // 2 MB mask bitmap (I-side words only)
__device__ float    g_rp[2][(size_t)BB * LL * NT];      // double-buffered row partials
__device__ float    g_Lm[2][BB * LL];                   // double-buffered multipliers
__device__ float    g_at[NSTEPS];                       // alpha * lr_alpha^t
__device__ float    g_bt[NSTEPS];                       // belt  * lr_belt^t
__device__ uchar2   g_pairs[NPAIRS];                    // (ti, tj) per linear pair id

// ---------------------------------------------------------------------------
// L2 evict_last cache-policy helpers (pin reused state in L2).
__device__ __forceinline__ unsigned long long mk_pol() {
    unsigned long long p;
    asm("createpolicy.fractional.L2::evict_last.b64 %0, 1.0;" : "=l"(p));
    return p;
}
__device__ __forceinline__ uint4 ld_u4_el(const uint4* a, unsigned long long pol) {
    uint4 v;
    asm("ld.global.L2::cache_hint.v4.u32 {%0,%1,%2,%3}, [%4], %5;"
        : "=r"(v.x), "=r"(v.y), "=r"(v.z), "=r"(v.w)
        : "l"(a), "l"(pol));
    return v;
}
__device__ __forceinline__ void st_u4_el(uint4* a, uint4 v, unsigned long long pol) {
    asm volatile("st.global.L2::cache_hint.v4.u32 [%0], {%1,%2,%3,%4}, %5;"
                 :: "l"(a), "r"(v.x), "r"(v.y), "r"(v.z), "r"(v.w), "l"(pol)
                 : "memory");
}
__device__ __forceinline__ uint2 ld_u2_el(const __half* a, unsigned long long pol) {
    uint2 v;
    asm("ld.global.L2::cache_hint.v2.u32 {%0,%1}, [%2], %3;"
        : "=r"(v.x), "=r"(v.y) : "l"(a), "l"(pol));
    return v;
}

// Pack two q-domain values (already in [0,65535]) via PRMT.
__device__ __forceinline__ unsigned qpackq(float a, float b) {
    return __byte_perm(__float2uint_rn(a), __float2uint_rn(b), 0x5410);
}

// ---------------------------------------------------------------------------
// One-time: step coefficients + pair table.
__global__ void coef_k(const float* __restrict__ alpha_p,
                       const float* __restrict__ belt_p,
                       const float* __restrict__ lra_p,
                       const float* __restrict__ lrb_p) {
    const int t = threadIdx.x;
    if (t < NSTEPS) {
        g_at[t] = (*alpha_p) * powf(*lra_p, (float)t);
        g_bt[t] = (*belt_p)  * powf(*lrb_p, (float)t);
    }
    if (t < NPAIRS) {
        int p = t, a = 0;
        while (p >= NT - a) { p -= NT - a; a++; }
        g_pairs[t] = make_uchar2((unsigned char)a, (unsigned char)(a + p));
    }
}

// ---------------------------------------------------------------------------
// Packed rho in pair layout (static, once). One block per pair.
__global__ __launch_bounds__(256) void rhop_k(const float* __restrict__ rho) {
    const uchar2 pr = g_pairs[blockIdx.x];
    const int ti = pr.x, tj = pr.y;
    const int tid = threadIdx.x;
    const int r = tid >> 3, c0 = (tid & 7) * 4;
    const float4 nat = *(const float4*)(rho + (ti * 32 + r) * LL + tj * 32 + c0);
    const float natv[4] = {nat.x, nat.y, nat.z, nat.w};
#pragma unroll
    for (int k = 0; k < 4; k++) {
        const float tr = rho[(tj * 32 + c0 + k) * LL + ti * 32 + r];
        g_RhoPp[blockIdx.x * 1024 + r * 32 + c0 + k] = __floats2half2_rn(natv[k], tr);
    }
}

// ---------------------------------------------------------------------------
// Init (slim): mask bitmap (I-side words only — J-side words were never read)
// and row-partials of A0 = sym(scores)*M. No state / Usym writes: the FIRST
// step reads scores directly and materializes S1 + Usym itself.
__global__ __launch_bounds__(256) void init2_k(const float* __restrict__ scores,
                                               const float* __restrict__ M) {
    const int  p  = blockIdx.x;
    const uchar2 pr = g_pairs[p];
    const int ti = pr.x, tj = pr.y;
    const int  b    = blockIdx.y;
    const bool diag = (ti == tj);
    const int  tid  = threadIdx.x;
    const int  r    = tid >> 3, g = tid & 7, c0 = g * 4;
    const int  warp = tid >> 5, lane = tid & 31;

    __shared__ float sS[32][33];
    __shared__ float sRed[8][32];

    const size_t rowI  = (size_t)(b * LL) + ti * 32 + r;
    const size_t baseI = rowI * LL + tj * 32 + c0;
    const size_t baseJ = ((size_t)(b * LL) + tj * 32 + r) * LL + ti * 32 + c0;

    const float4 scI = *(const float4*)(scores + baseI);
    const float4 scJ = *(const float4*)(scores + baseJ);   // == scI region for diag
    const float4 mI4 = *(const float4*)(M + baseI);

    sS[r][c0 + 0] = scJ.x; sS[r][c0 + 1] = scJ.y;
    sS[r][c0 + 2] = scJ.z; sS[r][c0 + 3] = scJ.w;

    // Pack mask bits (M is exactly 0.0/1.0). I-side words only.
    unsigned wI = (((mI4.x > 0.5f) ? 1u : 0u) | ((mI4.y > 0.5f) ? 2u : 0u) |
                   ((mI4.z > 0.5f) ? 4u : 0u) | ((mI4.w > 0.5f) ? 8u : 0u)) << c0;
    wI |= __shfl_xor_sync(0xffffffffu, wI, 1, 8);
    wI |= __shfl_xor_sync(0xffffffffu, wI, 2, 8);
    wI |= __shfl_xor_sync(0xffffffffu, wI, 4, 8);
    if (g == 0) g_Mbits[rowI * NT + tj] = wI;

    __syncthreads();

    const float scIv[4] = {scI.x, scI.y, scI.z, scI.w};
    const float mIv[4]  = {mI4.x, mI4.y, mI4.z, mI4.w};
    float a2v[4];
#pragma unroll
    for (int k = 0; k < 4; k++) {
        const float avg = 0.5f * (scIv[k] + sS[c0 + k][r]);
        a2v[k] = avg * mIv[k];                  // exact fp32 A0 values
    }

    // Row partials of A0 (buffer 1: step 0 reads (0+1)&1 = 1).
    {
        float v = (a2v[0] + a2v[1]) + (a2v[2] + a2v[3]);
        v += __shfl_down_sync(0xffffffffu, v, 4, 8);
        v += __shfl_down_sync(0xffffffffu, v, 2, 8);
        v += __shfl_down_sync(0xffffffffu, v, 1, 8);
        if (g == 0) g_rp[1][rowI * NT + tj] = v;
    }
    if (!diag) {
#pragma unroll
        for (int k = 0; k < 4; k++) {
            float v = a2v[k];
            v += __shfl_xor_sync(0xffffffffu, v, 16);
            v += __shfl_xor_sync(0xffffffffu, v, 8);
            if (lane < 8) sRed[warp][c0 + k] = v;
        }
        __syncthreads();
        if (tid < 32) {
            float s2 = 0.f;
#pragma unroll
            for (int w = 0; w < 8; w++) s2 += sRed[w][tid];
            g_rp[1][((size_t)(b * LL) + tj * 32 + tid) * NT + ti] = s2;
        }
    }
}

// ---------------------------------------------------------------------------
// FIRST proximal step (t = 0), 4 batches per block. Reads scores directly
// (A_hat0 == scores), computes Usym on the fly and writes it (fp16, pair
// layout), applies the t=0 update, writes quantized pair state S1.
__global__ __launch_bounds__(256, 4) void stepF_k(const float* __restrict__ scores,
                                                  const float* __restrict__ s_p,
                                                  const float* __restrict__ w_p) {
    const int  p  = blockIdx.x;
    const uchar2 pr = g_pairs[p];
    const int ti = pr.x, tj = pr.y;
    const int  b0   = blockIdx.y * 4;
    const bool diag = (ti == tj);
    const int  tid  = threadIdx.x;
    const int  r    = tid >> 3, g = tid & 7, c0 = g * 4;
    const int  warp = tid >> 5, lane = tid & 31;

    __shared__ float sS[4][32][33];   // scores J-side staging (transposed read)
    __shared__ float sRed[4][8][32];
    __shared__ float sC[256];

    const unsigned long long pol = mk_pol();

    const unsigned pb0  = (unsigned)(b0 * NPAIRS + p);
    const unsigned eoff = (unsigned)(r * 8 + g);
    const unsigned uoff = (unsigned)(r * 32 + c0);

    const float at  = g_at[0];
    const float atq = at * QSCALE;
    const float sv  = *s_p;
    const float wv  = *w_p;

    // Hoist score loads; stage J-side into shared for transposed access.
    float4 scI[4];
#pragma unroll
    for (int bb = 0; bb < 4; bb++) {
        const int b = b0 + bb;
        const size_t baseI = ((size_t)(b * LL) + ti * 32 + r) * LL + tj * 32 + c0;
        const size_t baseJ = ((size_t)(b * LL) + tj * 32 + r) * LL + ti * 32 + c0;
        scI[bb] = *(const float4*)(scores + baseI);
        const float4 scJ = *(const float4*)(scores + baseJ);
        sS[bb][r][c0 + 0] = scJ.x; sS[bb][r][c0 + 1] = scJ.y;
        sS[bb][r][c0 + 2] = scJ.z; sS[bb][r][c0 + 3] = scJ.w;
    }

    // Shared thresholds: rho * at, q-domain.
    float thx[4], thy[4];
    {
        const uint4 rp4 = *(const uint4*)(g_RhoPp + (unsigned)(p * 1024) + uoff);
        const __half2* rh = (const __half2*)&rp4;
#pragma unroll
        for (int k = 0; k < 4; k++) {
            const float2 rk = __half22float2(rh[k]);
            thx[k] = rk.x * atq;
            thy[k] = rk.y * atq;
        }
    }

    // --- per-row c (and Lm_0): all 256 threads, one row each, deterministic ---
    {
        const int batch = tid >> 6;
        const int idx   = tid & 63;
        const int b     = b0 + batch;
        const int rowl  = (idx < 32) ? (ti * 32 + idx) : (tj * 32 + (idx - 32));
        const unsigned ro = (unsigned)(b * LL + rowl);
        const float* rpr = g_rp[1] + ro * (unsigned)NT;
        const float4 p0 = *(const float4*)(rpr + 0);
        const float4 p1 = *(const float4*)(rpr + 4);
        const float4 p2 = *(const float4*)(rpr + 8);
        const float4 p3 = *(const float4*)(rpr + 12);
        const float v = (((p0.x + p0.y) + (p0.z + p0.w)) +
                         ((p1.x + p1.y) + (p1.z + p1.w))) +
                        (((p2.x + p2.y) + (p2.z + p2.w)) +
                         ((p3.x + p3.y) + (p3.z + p3.w)));
        const float rd   = v - 1.0f;
        const float rpos = fmaxf(rd, 0.f);
        const float lm   = wv * rpos;
        const float sg   = (rd > 0.f) ? 1.f : ((rd < 0.f) ? -1.f : 0.f);
        sC[tid] = lm * sg;
        if (diag && idx < 32) g_Lm[0][ro] = lm;
    }
    __syncthreads();   // covers sS staging + sC

    constexpr float HQ = 0.5f * QINV;
    float* __restrict__ rpout = g_rp[0];

#pragma unroll
    for (int bb = 0; bb < 4; bb++) {
        const int b = b0 + bb;
        const unsigned pb = pb0 + (unsigned)(bb * NPAIRS);
        const unsigned mw =
            g_Mbits[(unsigned)(b * LL + ti * 32 + r) * (unsigned)NT + tj];
        const float*   cb = sC + bb * 64;
        const float    ci = cb[r];
        const float4  cj4 = *(const float4*)(cb + 32 + c0);
        const float   cjv[4] = {cj4.x, cj4.y, cj4.z, cj4.w};
        const float   spv[4] = {scI[bb].x, scI[bb].y, scI[bb].z, scI[bb].w};

        uint4 outq;
        unsigned* oq = (unsigned*)&outq;
        float uu[4];
        float v = 0.f;
        float a2q[4];
#pragma unroll
        for (int k = 0; k < 4; k++) {
            const float stv = sS[bb][c0 + k][r];       // scores[j, i]
            const float avg = 0.5f * (spv[k] + stv);
            uu[k] = avg - sv;
            const bool  mk   = (mw >> (c0 + k)) & 1u;
            const float mult = mk ? fmaf(at, uu[k] - (ci + cjv[k]), 1.f) : 1.f;
            const float pv = fminf(fmaxf(fabsf(spv[k] * mult) * QSCALE - thx[k], 0.f), QSCALE);
            const float tv = fminf(fmaxf(fabsf(stv * mult) * QSCALE - thy[k], 0.f), QSCALE);
            oq[k]  = qpackq(pv, tv);
            a2q[k] = mk ? (pv + tv) : 0.f;
            v += a2q[k];
        }

        // Write Usym (fp16, pair layout) for all later steps.
        {
            __half2 h01 = __floats2half2_rn(uu[0], uu[1]);
            __half2 h23 = __floats2half2_rn(uu[2], uu[3]);
            uint2 pk; pk.x = *(unsigned*)&h01; pk.y = *(unsigned*)&h23;
            *(uint2*)(g_Uh + pb * 1024u + uoff) = pk;
        }
        st_u4_el(g_S + pb * 256u + eoff, outq, pol);

        // Row partials of A1, ti rows.
        v += __shfl_down_sync(0xffffffffu, v, 4, 8);
        v += __shfl_down_sync(0xffffffffu, v, 2, 8);
        v += __shfl_down_sync(0xffffffffu, v, 1, 8);
        if (g == 0)
            rpout[(unsigned)(b * LL + ti * 32 + r) * (unsigned)NT + tj] = v * HQ;
        if (!diag) {
#pragma unroll
            for (int k = 0; k < 4; k++) {
                float w2 = a2q[k];
                w2 += __shfl_xor_sync(0xffffffffu, w2, 16);
                w2 += __shfl_xor_sync(0xffffffffu, w2, 8);
                if (lane < 8) sRed[bb][warp][c0 + k] = w2;
            }
        }
    }

    if (!diag) {
        __syncthreads();
        if (tid < 128) {
            const int bb = tid >> 5, col = tid & 31;
            float s2 = 0.f;
#pragma unroll
            for (int w = 0; w < 8; w++) s2 += sRed[bb][w][col];
            rpout[(unsigned)((b0 + bb) * LL + tj * 32 + col) * (unsigned)NT + ti] = s2 * HQ;
        }
    }
}

// ---------------------------------------------------------------------------
// Mid proximal step (t = 1..18), 4 batches per block. Pair-packed u16 state,
// q-domain arithmetic. Per-block deterministic recompute of c (and Lm_t).
__global__ __launch_bounds__(256, 4) void step4_k(int t) {
    const int  p  = blockIdx.x;
    const uchar2 pr = g_pairs[p];
    const int ti = pr.x, tj = pr.y;
    const int  b0   = blockIdx.y * 4;
    const bool diag = (ti == tj);
    const int  tid  = threadIdx.x;
    const int  r    = tid >> 3, g = tid & 7, c0 = g * 4;
    const int  warp = tid >> 5, lane = tid & 31;

    __shared__ float sRed[4][8][32];
    __shared__ float sC[256];

    const unsigned long long pol = mk_pol();

    const unsigned pb0  = (unsigned)(b0 * NPAIRS + p);
    const unsigned eoff = (unsigned)(r * 8 + g);
    const unsigned uoff = (unsigned)(r * 32 + c0);

    // Hoist the long-latency loads (state + Usym) for MLP (12 LDGs in flight).
    uint4 sq[4];
    uint2 up[4];
#pragma unroll
    for (int bb = 0; bb < 4; bb++) {
        const unsigned pb = pb0 + (unsigned)(bb * NPAIRS);
        sq[bb] = ld_u4_el(g_S + pb * 256u + eoff, pol);
        up[bb] = ld_u2_el(g_Uh + pb * 1024u + uoff, pol);
    }

    const float at  = g_at[t];
    const float atq = at * QSCALE;

    // Shared thresholds: rho * at, q-domain.
    float thx[4], thy[4];
    {
        const uint4 rp4 = *(const uint4*)(g_RhoPp + (unsigned)(p * 1024) + uoff);
        const __half2* rh = (const __half2*)&rp4;
#pragma unroll
        for (int k = 0; k < 4; k++) {
            const float2 rk = __half22float2(rh[k]);
            thx[k] = rk.x * atq;
            thy[k] = rk.y * atq;
        }
    }

    // --- per-row c (and Lm_t): all 256 threads, one row each, deterministic ---
    {
        const int batch = tid >> 6;
        const int idx   = tid & 63;
        const int b     = b0 + batch;
        const int rowl  = (idx < 32) ? (ti * 32 + idx) : (tj * 32 + (idx - 32));
        const unsigned ro = (unsigned)(b * LL + rowl);
        const float* rpr = g_rp[(t + 1) & 1] + ro * (unsigned)NT;
        const float4 p0 = *(const float4*)(rpr + 0);
        const float4 p1 = *(const float4*)(rpr + 4);
        const float4 p2 = *(const float4*)(rpr + 8);
        const float4 p3 = *(const float4*)(rpr + 12);
        const float v = (((p0.x + p0.y) + (p0.z + p0.w)) +
                         ((p1.x + p1.y) + (p1.z + p1.w))) +
                        (((p2.x + p2.y) + (p2.z + p2.w)) +
                         ((p3.x + p3.y) + (p3.z + p3.w)));
        const float rd   = v - 1.0f;
        const float rpos = fmaxf(rd, 0.f);
        const float lm   = g_Lm[(t + 1) & 1][ro] + g_bt[t - 1] * rpos;
        const float sg   = (rd > 0.f) ? 1.f : ((rd < 0.f) ? -1.f : 0.f);
        sC[tid] = lm * sg;
        if (diag && idx < 32) g_Lm[t & 1][ro] = lm;
    }
    __syncthreads();

    constexpr float HQ = 0.5f * QINV;
    float* __restrict__ rpout = g_rp[t & 1];

#pragma unroll
    for (int bb = 0; bb < 4; bb++) {
        const unsigned mw =
            g_Mbits[(unsigned)((b0 + bb) * LL + ti * 32 + r) * (unsigned)NT + tj];
        const float*   cb = sC + bb * 64;
        const float    ci = cb[r];
        const float4  cj4 = *(const float4*)(cb + 32 + c0);
        const float   cjv[4] = {cj4.x, cj4.y, cj4.z, cj4.w};
        const unsigned sqs[4] = {sq[bb].x, sq[bb].y, sq[bb].z, sq[bb].w};
        const float2 u01 = __half22float2(*(const __half2*)&up[bb].x);
        const float2 u23 = __half22float2(*(const __half2*)&up[bb].y);
        const float uv[4] = {u01.x, u01.y, u23.x, u23.y};

        uint4 outq;
        unsigned* oq = (unsigned*)&outq;
        float v = 0.f;
        float a2q[4];
#pragma unroll
        for (int k = 0; k < 4; k++) {
            const bool  mk   = (mw >> (c0 + k)) & 1u;
            const float du   = uv[k] - (ci + cjv[k]);
            const float mult = mk ? fmaf(at, du, 1.f) : 1.f;
            const float spq  = (float)(sqs[k] & 0xffffu);
            const float stq  = (float)(sqs[k] >> 16);
            const float pv = fminf(fmaxf(fabsf(spq * mult) - thx[k], 0.f), QSCALE);
            const float tv = fminf(fmaxf(fabsf(stq * mult) - thy[k], 0.f), QSCALE);
            oq[k]  = qpackq(pv, tv);
            a2q[k] = mk ? (pv + tv) : 0.f;
            v += a2q[k];
        }

        st_u4_el(g_S + (pb0 + (unsigned)(bb * NPAIRS)) * 256u + eoff, outq, pol);

        v += __shfl_down_sync(0xffffffffu, v, 4, 8);
        v += __shfl_down_sync(0xffffffffu, v, 2, 8);
        v += __shfl_down_sync(0xffffffffu, v, 1, 8);
        if (g == 0)
            rpout[(unsigned)((b0 + bb) * LL + ti * 32 + r) * (unsigned)NT + tj] = v * HQ;
        if (!diag) {
#pragma unroll
            for (int k = 0; k < 4; k++) {
                float w2 = a2q[k];
                w2 += __shfl_xor_sync(0xffffffffu, w2, 16);
                w2 += __shfl_xor_sync(0xffffffffu, w2, 8);
                if (lane < 8) sRed[bb][warp][c0 + k] = w2;
            }
        }
    }

    if (!diag) {
        __syncthreads();
        if (tid < 128) {
            const int bb = tid >> 5, col = tid & 31;
            float s2 = 0.f;
#pragma unroll
            for (int w = 0; w < 8; w++) s2 += sRed[bb][w][col];
            rpout[(unsigned)((b0 + bb) * LL + tj * 32 + col) * (unsigned)NT + ti] = s2 * HQ;
        }
    }
}

// ---------------------------------------------------------------------------
// Last proximal step: computes A2 and writes dense output only.
__global__ __launch_bounds__(256, 7) void stepL_k(int t, float* __restrict__ out) {
    const int  p  = blockIdx.x;
    const uchar2 pr = g_pairs[p];
    const int ti = pr.x, tj = pr.y;
    const int  b    = blockIdx.y;
    const bool diag = (ti == tj);
    const int  tid  = threadIdx.x;
    const int  r    = tid >> 3, g = tid & 7, c0 = g * 4;

    __shared__ float sStage[32][33];
    __shared__ float sC[64];

    const size_t rowI = (size_t)(b * LL) + ti * 32 + r;
    const unsigned long long pol = mk_pol();

    const size_t pbase = (size_t)(b * NPAIRS + p);
    const size_t sidx  = pbase * 256 + r * 8 + g;
    const uint4  sq  = ld_u4_el(g_S + sidx, pol);
    const uint2  up  = ld_u2_el(g_Uh + pbase * 1024 + r * 32 + c0, pol);
    const uint4  rp4 = *(const uint4*)(g_RhoPp + p * 1024 + r * 32 + c0);
    const unsigned mw = g_Mbits[rowI * NT + tj];

    const float at  = g_at[t];
    const float atq = at * QSCALE;

    if (tid < 64) {
        const int rowl = (tid < 32) ? (ti * 32 + tid) : (tj * 32 + (tid - 32));
        const float* rpr = g_rp[(t + 1) & 1] + ((size_t)(b * LL) + rowl) * NT;
        const float4 p0 = *(const float4*)(rpr + 0);
        const float4 p1 = *(const float4*)(rpr + 4);
        const float4 p2 = *(const float4*)(rpr + 8);
        const float4 p3 = *(const float4*)(rpr + 12);
        const float v = (((p0.x + p0.y) + (p0.z + p0.w)) +
                         ((p1.x + p1.y) + (p1.z + p1.w))) +
                        (((p2.x + p2.y) + (p2.z + p2.w)) +
                         ((p3.x + p3.y) + (p3.z + p3.w)));
        const float rd   = v - 1.0f;
        const float rpos = fmaxf(rd, 0.f);
        const float lm = g_Lm[(t + 1) & 1][b * LL + rowl] + g_bt[t - 1] * rpos;
        const float sg = (rd > 0.f) ? 1.f : ((rd < 0.f) ? -1.f : 0.f);
        sC[tid] = lm * sg;
    }
    __syncthreads();

    const float ci = sC[r];
    const float4 cj4 = *(const float4*)(sC + 32 + c0);
    const float cjv[4] = {cj4.x, cj4.y, cj4.z, cj4.w};
    const unsigned sqs[4] = {sq.x, sq.y, sq.z, sq.w};
    const __half2* rh = (const __half2*)&rp4;
    const float2 u01 = __half22float2(*(const __half2*)&up.x);
    const float2 u23 = __half22float2(*(const __half2*)&up.y);
    const float uv[4] = {u01.x, u01.y, u23.x, u23.y};

    constexpr float HQ = 0.5f * QINV;
    float a2[4];
#pragma unroll
    for (int k = 0; k < 4; k++) {
        const bool  mk   = (mw >> (c0 + k)) & 1u;
        const float du   = uv[k] - (ci + cjv[k]);
        const float mult = mk ? fmaf(at, du, 1.f) : 1.f;
        const float2 rk  = __half22float2(rh[k]);
        const float spq  = (float)(sqs[k] & 0xffffu);
        const float stq  = (float)(sqs[k] >> 16);
        const float pv = fminf(fmaxf(fabsf(spq * mult) - rk.x * atq, 0.f), QSCALE);
        const float tv = fminf(fmaxf(fabsf(stq * mult) - rk.y * atq, 0.f), QSCALE);
        a2[k] = mk ? (pv + tv) * HQ : 0.f;
        sStage[c0 + k][r] = a2[k];
    }

    const size_t baseI = rowI * LL + tj * 32 + c0;
    *(float4*)(out + baseI) = make_float4(a2[0], a2[1], a2[2], a2[3]);
    __syncthreads();
    if (!diag) {
        const size_t baseJ = ((size_t)(b * LL) + tj * 32 + r) * LL + ti * 32 + c0;
        *(float4*)(out + baseJ) = make_float4(sStage[r][c0 + 0], sStage[r][c0 + 1],
                                              sStage[r][c0 + 2], sStage[r][c0 + 3]);
    }
}

// ---------------------------------------------------------------------------
extern "C" void kernel_launch(void* const* d_in, const int* in_sizes, int n_in,
                              void* d_out, int out_size) {
    const float* scores  = (const float*)d_in[0];
    const float* M       = (const float*)d_in[1];
    const float* s_p     = (const float*)d_in[2];
    const float* w_p     = (const float*)d_in[3];
    const float* rho     = (const float*)d_in[4];
    const float* alpha_p = (const float*)d_in[5];
    const float* belt_p  = (const float*)d_in[6];
    const float* lra_p   = (const float*)d_in[7];
    const float* lrb_p   = (const float*)d_in[8];
    float* out = (float*)d_out;
    (void)in_sizes; (void)n_in; (void)out_size;

    coef_k<<<1, 256>>>(alpha_p, belt_p, lra_p, lrb_p);
    rhop_k<<<NPAIRS, 256>>>(rho);

    init2_k<<<dim3(NPAIRS, BB), 256>>>(scores, M);

    dim3 grid4(NPAIRS, BB / 4);
    stepF_k<<<grid4, 256>>>(scores, s_p, w_p);
    for (int t = 1; t < NSTEPS - 1; t++)
        step4_k<<<grid4, 256>>>(t);
    stepL_k<<<dim3(NPAIRS, BB), 256>>>(NSTEPS - 1, out);
}